// round 13
// baseline (speedup 1.0000x reference)
#include <cuda_runtime.h>
#include <cuda_fp16.h>
#include <cstdint>

// ============================================================
// SparseModel: 32 MLPs (64 -> 128 -> 128 -> 128 -> 1, swish)
// 2 CTAs/SM occupancy build: 512 thr, smem 116224 (= W 80K + act 32K + bias 1.5K),
// warp tile 32x32 in-place single buffer, tanh-swish (1 MUFU), 64-reg cap.
// Head: Wo/bo via __ldg; partials live in EACH GROUP'S OWN k-hi act region
// (rg*4096 bytes — fixes R12's cross-group race/NaN).
// ============================================================

#define THREADS 512
#define TILES_PER_CTA 4      // grid 2048 = 32 subnets x 64 groups of 512 rows

// ---- smem layout ----
static constexpr int SM_ACT  = 0;        // act [128 x 128 fp16] swizzled (32768)
static constexpr int SM_W1   = 32768;    // W1  [128n x 64k fp16]  (16384)
static constexpr int SM_WH0  = 49152;    // Wh0 [128n x 128k fp16] (32768)
static constexpr int SM_WH1  = 81920;    // Wh1                    (32768)
static constexpr int SM_BIAS = 114688;   // 3 x 128 floats         (1536)
static constexpr int SM_TOTAL = 116224;  // x2 = 232448 <= 233472 SM limit

// head partials: group rg uses bytes [16384 + rg*4096, +512) — inside its OWN
// rows' k>=64 act region (rows 32rg..32rg+7, k 64..95), ordered by the group barrier
static constexpr int SM_PARTOFF = 16384;

// ---- helpers ----
__device__ __forceinline__ uint32_t smem_to_u32(const void* p) {
    uint32_t a;
    asm("{ .reg .u64 t; cvta.to.shared.u64 t, %1; cvt.u32.u64 %0, t; }" : "=r"(a) : "l"(p));
    return a;
}
__device__ __forceinline__ uint32_t swz(uint32_t b) { return b ^ ((b >> 3) & 0x70u); }
__device__ __forceinline__ uint32_t toff(int r, int k) {
    return (uint32_t)(((((k >> 6) << 4) + (r >> 3)) << 10) | ((r & 7) << 7) | ((k & 63) << 1));
}

#define LDSM_X4(r, addr) \
    asm volatile("ldmatrix.sync.aligned.m8n8.x4.shared.b16 {%0,%1,%2,%3}, [%4];" \
        : "=r"((r)[0]), "=r"((r)[1]), "=r"((r)[2]), "=r"((r)[3]) : "r"(addr))
#define MMA16816(d, a, b) \
    asm volatile("mma.sync.aligned.m16n8k16.row.col.f32.f16.f16.f32 " \
        "{%0,%1,%2,%3}, {%4,%5,%6,%7}, {%8,%9}, {%0,%1,%2,%3};" \
        : "+f"((d)[0]), "+f"((d)[1]), "+f"((d)[2]), "+f"((d)[3]) \
        : "r"((a)[0]), "r"((a)[1]), "r"((a)[2]), "r"((a)[3]), "r"((b)[0]), "r"((b)[1]))
#define BARG(id) asm volatile("bar.sync %0, 128;" :: "r"(id) : "memory")

// swish via tanh.approx: swish(v) = h*tanh(h)+h with h = v/2   (1 MUFU)
__device__ __forceinline__ float swishf(float v) {
    float t;
    const float h = 0.5f * v;
    asm("tanh.approx.f32 %0, %1;" : "=f"(t) : "f"(h));
    return fmaf(h, t, h);
}

// warp-32x32 layer mainloop; acc[mt][nt][e]
template <int NCH>
__device__ __forceinline__ void layer_mma(
    float acc[2][4][4], uint32_t actB, uint32_t wB,
    uint32_t aP0, uint32_t aX, int ka,
    uint32_t bRow0, uint32_t bX, int kb4)
{
    #pragma unroll
    for (int c = 0; c < NCH; ++c) {
        const uint32_t kA  = (uint32_t)(c * 16 + ka);
        const uint32_t kxA = ((kA >> 6) << 14) + (((kA & 63) << 1) ^ aX);
        const uint32_t kB  = (uint32_t)(c * 16 + kb4);
        const uint32_t kxB = ((kB >> 6) << 14) + (((kB & 63) << 1) ^ bX);

        uint32_t a0[4], a1[4], bf[4][2];
        LDSM_X4(a0, actB + aP0 + kxA);
        LDSM_X4(a1, actB + aP0 + (2u << 10) + kxA);
        #pragma unroll
        for (int np = 0; np < 2; np++) {
            uint32_t q4[4];
            LDSM_X4(q4, wB + bRow0 + ((uint32_t)np << 11) + kxB);
            bf[2*np][0]   = q4[0]; bf[2*np][1]   = q4[1];
            bf[2*np+1][0] = q4[2]; bf[2*np+1][1] = q4[3];
        }
        #pragma unroll
        for (int nt = 0; nt < 4; nt++) {
            MMA16816(acc[0][nt], a0, bf[nt]);
            MMA16816(acc[1][nt], a1, bf[nt]);
        }
    }
}

__global__ void __launch_bounds__(THREADS, 2)
mlp_fused_kernel(const float* __restrict__ x,  const float* __restrict__ W1,
                 const float* __restrict__ b1, const float* __restrict__ Wh,
                 const float* __restrict__ bh, const float* __restrict__ Wo,
                 const float* __restrict__ bo, float* __restrict__ out)
{
    extern __shared__ char smc[];
    const uint32_t smb = smem_to_u32(smc);
    const int tid = threadIdx.x;
    const int wid = tid >> 5;
    const int lane = tid & 31;
    const int o = blockIdx.x & 31;       // subnet
    const int g = blockIdx.x >> 5;       // group of 512 rows

    const int rg = wid >> 2;             // row group (32 rows)
    const int wq = wid & 3;              // column quarter (32 cols)
    const int barid = 1 + rg;            // named barriers 1..4 (128 threads each)

    // ---- stage weights (fp16, single rounding; float4 global reads) ----
    {
        const float* W1p = W1 + o * 64 * 128;
        for (int idx = tid; idx < 64 * 128 / 4; idx += THREADS) {
            int k = idx >> 5, j = (idx & 31) << 2;    // W1[o][k][j..j+3] -> B[n=j..][k]
            float4 w = reinterpret_cast<const float4*>(W1p)[idx];
            *reinterpret_cast<__half*>(smc + SM_W1 + swz(toff(j + 0, k))) = __float2half_rn(w.x);
            *reinterpret_cast<__half*>(smc + SM_W1 + swz(toff(j + 1, k))) = __float2half_rn(w.y);
            *reinterpret_cast<__half*>(smc + SM_W1 + swz(toff(j + 2, k))) = __float2half_rn(w.z);
            *reinterpret_cast<__half*>(smc + SM_W1 + swz(toff(j + 3, k))) = __float2half_rn(w.w);
        }
        #pragma unroll
        for (int l = 0; l < 2; l++) {
            const float* Wp = Wh + ((size_t)l * 32 + o) * 128 * 128;
            const int base = l ? SM_WH1 : SM_WH0;
            for (int idx = tid; idx < 128 * 128 / 4; idx += THREADS) {
                int k = idx >> 5, j = (idx & 31) << 2;
                float4 w = reinterpret_cast<const float4*>(Wp)[idx];
                *reinterpret_cast<__half*>(smc + base + swz(toff(j + 0, k))) = __float2half_rn(w.x);
                *reinterpret_cast<__half*>(smc + base + swz(toff(j + 1, k))) = __float2half_rn(w.y);
                *reinterpret_cast<__half*>(smc + base + swz(toff(j + 2, k))) = __float2half_rn(w.z);
                *reinterpret_cast<__half*>(smc + base + swz(toff(j + 3, k))) = __float2half_rn(w.w);
            }
        }
        for (int j = tid; j < 128; j += THREADS) {
            reinterpret_cast<float*>(smc + SM_BIAS)[j]       = b1[o * 128 + j];
            reinterpret_cast<float*>(smc + SM_BIAS)[128 + j] = bh[(size_t)o * 128 + j];
            reinterpret_cast<float*>(smc + SM_BIAS)[256 + j] = bh[((size_t)32 + o) * 128 + j];
        }
    }
    __syncthreads();

    const float* sbias = reinterpret_cast<const float*>(smc + SM_BIAS);
    float* pa = reinterpret_cast<float*>(smc + SM_PARTOFF + rg * 4096);   // FIXED: byte stride

    // ---- ldmatrix lane addressing ----
    const int ra0 = rg * 32 + ((lane >> 3) & 1) * 8 + (lane & 7);
    const uint32_t aP0 = (uint32_t)(((ra0 >> 3) << 10) | ((ra0 & 7) << 7));
    const uint32_t aX  = (uint32_t)((lane & 7) << 4);
    const int ka = (lane >> 4) * 8;
    const int quad = lane >> 3;
    const int nb   = ((quad >> 1) << 3) + (lane & 7);
    const int kb4  = (quad & 1) << 3;
    const uint32_t bRow0 = (uint32_t)(((wq * 4 + (nb >> 3)) << 10) | ((nb & 7) << 7));
    const uint32_t bX    = (uint32_t)((lane & 7) << 4);

    const uint32_t actB = smb + SM_ACT;
    const int q = lane >> 2;

    for (int t = 0; t < TILES_PER_CTA; t++) {
        const int m0 = (g * TILES_PER_CTA + t) * 128;

        // ---- stage X rows for this group: [32 rows x 64 k] fp32 -> fp16 ----
        {
            const int p = wq * 32 + lane;             // 0..127 within group
            const int r = rg * 32 + (p >> 2);         // row
            const int kbx = (p & 3) << 4;             // k base
            const float4* xp = reinterpret_cast<const float4*>(x + (size_t)(m0 + r) * 64 + kbx);
            #pragma unroll
            for (int qq = 0; qq < 4; qq++) {
                float4 v = xp[qq];
                __half2 hh01 = __halves2half2(__float2half_rn(v.x), __float2half_rn(v.y));
                __half2 hh23 = __halves2half2(__float2half_rn(v.z), __float2half_rn(v.w));
                uint32_t off0 = swz(toff(r, kbx + 4 * qq));
                uint32_t off1 = swz(toff(r, kbx + 4 * qq + 2));
                *reinterpret_cast<uint32_t*>(smc + SM_ACT + off0) = *reinterpret_cast<uint32_t*>(&hh01);
                *reinterpret_cast<uint32_t*>(smc + SM_ACT + off1) = *reinterpret_cast<uint32_t*>(&hh23);
            }
        }
        BARG(barid);                 // (1) X visible

        // ---- layers 0 and 1: MMA then in-place epilogue ----
        #pragma unroll
        for (int l = 0; l < 2; l++) {
            float acc[2][4][4];
            #pragma unroll
            for (int mt = 0; mt < 2; mt++)
                #pragma unroll
                for (int nt = 0; nt < 4; nt++)
                    #pragma unroll
                    for (int e = 0; e < 4; e++) acc[mt][nt][e] = 0.0f;

            if (l == 0)
                layer_mma<4>(acc, actB, smb + SM_W1,  aP0, aX, ka, bRow0, bX, kb4);
            else
                layer_mma<8>(acc, actB, smb + SM_WH0, aP0, aX, ka, bRow0, bX, kb4);

            BARG(barid);             // group done reading act before rewrite
            const float* bias = sbias + l * 128;
            #pragma unroll
            for (int mt = 0; mt < 2; mt++) {
                const uint32_t rp0 = (uint32_t)(((rg * 4 + mt * 2) << 10) | (q << 7));
                const uint32_t rp1 = rp0 + (1u << 10);
                #pragma unroll
                for (int nt = 0; nt < 4; nt++) {
                    const int cc = wq * 32 + nt * 8 + (lane & 3) * 2;
                    const float b0v = bias[cc], b1v = bias[cc + 1];
                    float s0 = swishf(acc[mt][nt][0] + b0v);
                    float s1 = swishf(acc[mt][nt][1] + b1v);
                    float s2 = swishf(acc[mt][nt][2] + b0v);
                    float s3 = swishf(acc[mt][nt][3] + b1v);
                    __half2 hh01 = __halves2half2(__float2half_rn(s0), __float2half_rn(s1));
                    __half2 hh23 = __halves2half2(__float2half_rn(s2), __float2half_rn(s3));
                    const uint32_t kx = (uint32_t)(((cc >> 6) << 14) +
                                        (((cc & 63) << 1) ^ (q << 4)));
                    *reinterpret_cast<uint32_t*>(smc + SM_ACT + rp0 + kx) = *reinterpret_cast<uint32_t*>(&hh01);
                    *reinterpret_cast<uint32_t*>(smc + SM_ACT + rp1 + kx) = *reinterpret_cast<uint32_t*>(&hh23);
                }
            }
            BARG(barid);             // writes visible before next layer's reads
        }

        // ---- layer 2 + fused scalar head ----
        {
            float acc[2][4][4];
            #pragma unroll
            for (int mt = 0; mt < 2; mt++)
                #pragma unroll
                for (int nt = 0; nt < 4; nt++)
                    #pragma unroll
                    for (int e = 0; e < 4; e++) acc[mt][nt][e] = 0.0f;

            layer_mma<8>(acc, actB, smb + SM_WH1, aP0, aX, ka, bRow0, bX, kb4);

            const float* wo = Wo + o * 128;
            float ps[4] = {0.f, 0.f, 0.f, 0.f};
            #pragma unroll
            for (int mt = 0; mt < 2; mt++) {
                #pragma unroll
                for (int nt = 0; nt < 4; nt++) {
                    const int cc = wq * 32 + nt * 8 + (lane & 3) * 2;
                    const float b0v = sbias[256 + cc], b1v = sbias[256 + cc + 1];
                    const float2 wv = __ldg(reinterpret_cast<const float2*>(wo + cc));
                    ps[mt * 2 + 0] += swishf(acc[mt][nt][0] + b0v) * wv.x
                                    + swishf(acc[mt][nt][1] + b1v) * wv.y;
                    ps[mt * 2 + 1] += swishf(acc[mt][nt][2] + b0v) * wv.x
                                    + swishf(acc[mt][nt][3] + b1v) * wv.y;
                }
            }
            #pragma unroll
            for (int i = 0; i < 4; i++) {
                ps[i] += __shfl_xor_sync(0xffffffffu, ps[i], 1);
                ps[i] += __shfl_xor_sync(0xffffffffu, ps[i], 2);
            }
            BARG(barid);             // group's layer-2 act reads done -> pa region reusable
            if ((lane & 3) == 0) {
                const int r = lane >> 2;              // 0..7
                float* sp = pa + wq * 32;
                sp[r]      = ps[0];
                sp[r + 8]  = ps[1];
                sp[r + 16] = ps[2];
                sp[r + 24] = ps[3];
            }
            BARG(barid);             // pa visible
            if (wq == 0) {
                float v = pa[lane] + pa[32 + lane] + pa[64 + lane] + pa[96 + lane];
                out[(size_t)(m0 + rg * 32 + lane) * 32 + o] = v + __ldg(bo + o);
            }
            // next tile's staging writes only bytes [0,16384) (k<64), disjoint
            // from pa; barrier (1) orders everything else.
        }
    }
}

extern "C" void kernel_launch(void* const* d_in, const int* in_sizes, int n_in,
                              void* d_out, int out_size) {
    const float* x  = (const float*)d_in[0];
    const float* W1 = (const float*)d_in[1];
    const float* b1 = (const float*)d_in[2];
    const float* Wh = (const float*)d_in[3];
    const float* bh = (const float*)d_in[4];
    const float* Wo = (const float*)d_in[5];
    const float* bo = (const float*)d_in[6];
    float* out = (float*)d_out;

    cudaFuncSetAttribute(mlp_fused_kernel,
                         cudaFuncAttributeMaxDynamicSharedMemorySize, SM_TOTAL);
    mlp_fused_kernel<<<2048, THREADS, SM_TOTAL>>>(x, W1, b1, Wh, bh, Wo, bo, out);
}

// round 14
// speedup vs baseline: 1.2311x; 1.2311x over previous
#include <cuda_runtime.h>
#include <cuda_fp16.h>
#include <cstdint>

// ============================================================
// SparseModel: 32 MLPs (64 -> 128 -> 128 -> 128 -> 1, swish)
// 2 CTAs/SM build, take 2: smem 114688 (W 80K + act 32K, NO bias array;
// (114688+1024)*2 = 231424 <= 233472 incl. per-CTA reservation).
// Grid 1024 (8 tiles/CTA) to keep weight staging amortized.
// Warp tile 32x32 in-place, tanh-swish, biases/Wo/bo via __ldg.
// ============================================================

#define THREADS 512
#define TILES_PER_CTA 8      // grid 1024 = 32 subnets x 32 groups of 1024 rows

// ---- smem layout ----
static constexpr int SM_ACT  = 0;        // act [128 x 128 fp16] swizzled (32768)
static constexpr int SM_W1   = 32768;    // W1  [128n x 64k fp16]  (16384)
static constexpr int SM_WH0  = 49152;    // Wh0 [128n x 128k fp16] (32768)
static constexpr int SM_WH1  = 81920;    // Wh1                    (32768)
static constexpr int SM_TOTAL = 114688;  // +1024 reserved, x2 = 231424 <= 233472

// head partials: group rg uses bytes [16384 + rg*4096, +512) — its OWN rows'
// k>=64 act region (rows 32rg..32rg+7, k 64..95); ordered by the group barrier
static constexpr int SM_PARTOFF = 16384;

// ---- helpers ----
__device__ __forceinline__ uint32_t smem_to_u32(const void* p) {
    uint32_t a;
    asm("{ .reg .u64 t; cvta.to.shared.u64 t, %1; cvt.u32.u64 %0, t; }" : "=r"(a) : "l"(p));
    return a;
}
__device__ __forceinline__ uint32_t swz(uint32_t b) { return b ^ ((b >> 3) & 0x70u); }
__device__ __forceinline__ uint32_t toff(int r, int k) {
    return (uint32_t)(((((k >> 6) << 4) + (r >> 3)) << 10) | ((r & 7) << 7) | ((k & 63) << 1));
}

#define LDSM_X4(r, addr) \
    asm volatile("ldmatrix.sync.aligned.m8n8.x4.shared.b16 {%0,%1,%2,%3}, [%4];" \
        : "=r"((r)[0]), "=r"((r)[1]), "=r"((r)[2]), "=r"((r)[3]) : "r"(addr))
#define MMA16816(d, a, b) \
    asm volatile("mma.sync.aligned.m16n8k16.row.col.f32.f16.f16.f32 " \
        "{%0,%1,%2,%3}, {%4,%5,%6,%7}, {%8,%9}, {%0,%1,%2,%3};" \
        : "+f"((d)[0]), "+f"((d)[1]), "+f"((d)[2]), "+f"((d)[3]) \
        : "r"((a)[0]), "r"((a)[1]), "r"((a)[2]), "r"((a)[3]), "r"((b)[0]), "r"((b)[1]))
#define BARG(id) asm volatile("bar.sync %0, 128;" :: "r"(id) : "memory")

// swish via tanh.approx: swish(v) = h*tanh(h)+h with h = v/2   (1 MUFU)
__device__ __forceinline__ float swishf(float v) {
    float t;
    const float h = 0.5f * v;
    asm("tanh.approx.f32 %0, %1;" : "=f"(t) : "f"(h));
    return fmaf(h, t, h);
}

// warp-32x32 layer mainloop; acc[mt][nt][e]
template <int NCH>
__device__ __forceinline__ void layer_mma(
    float acc[2][4][4], uint32_t actB, uint32_t wB,
    uint32_t aP0, uint32_t aX, int ka,
    uint32_t bRow0, uint32_t bX, int kb4)
{
    #pragma unroll
    for (int c = 0; c < NCH; ++c) {
        const uint32_t kA  = (uint32_t)(c * 16 + ka);
        const uint32_t kxA = ((kA >> 6) << 14) + (((kA & 63) << 1) ^ aX);
        const uint32_t kB  = (uint32_t)(c * 16 + kb4);
        const uint32_t kxB = ((kB >> 6) << 14) + (((kB & 63) << 1) ^ bX);

        uint32_t a0[4], a1[4], bf[4][2];
        LDSM_X4(a0, actB + aP0 + kxA);
        LDSM_X4(a1, actB + aP0 + (2u << 10) + kxA);
        #pragma unroll
        for (int np = 0; np < 2; np++) {
            uint32_t q4[4];
            LDSM_X4(q4, wB + bRow0 + ((uint32_t)np << 11) + kxB);
            bf[2*np][0]   = q4[0]; bf[2*np][1]   = q4[1];
            bf[2*np+1][0] = q4[2]; bf[2*np+1][1] = q4[3];
        }
        #pragma unroll
        for (int nt = 0; nt < 4; nt++) {
            MMA16816(acc[0][nt], a0, bf[nt]);
            MMA16816(acc[1][nt], a1, bf[nt]);
        }
    }
}

__global__ void __launch_bounds__(THREADS, 2)
mlp_fused_kernel(const float* __restrict__ x,  const float* __restrict__ W1,
                 const float* __restrict__ b1, const float* __restrict__ Wh,
                 const float* __restrict__ bh, const float* __restrict__ Wo,
                 const float* __restrict__ bo, float* __restrict__ out)
{
    extern __shared__ char smc[];
    const uint32_t smb = smem_to_u32(smc);
    const int tid = threadIdx.x;
    const int wid = tid >> 5;
    const int lane = tid & 31;
    const int o = blockIdx.x & 31;       // subnet
    const int g = blockIdx.x >> 5;       // group of 1024 rows

    const int rg = wid >> 2;             // row group (32 rows)
    const int wq = wid & 3;              // column quarter (32 cols)
    const int barid = 1 + rg;            // named barriers 1..4 (128 threads each)

    // ---- stage weights (fp16, single rounding; float4 global reads) ----
    {
        const float* W1p = W1 + o * 64 * 128;
        for (int idx = tid; idx < 64 * 128 / 4; idx += THREADS) {
            int k = idx >> 5, j = (idx & 31) << 2;    // W1[o][k][j..j+3] -> B[n=j..][k]
            float4 w = reinterpret_cast<const float4*>(W1p)[idx];
            *reinterpret_cast<__half*>(smc + SM_W1 + swz(toff(j + 0, k))) = __float2half_rn(w.x);
            *reinterpret_cast<__half*>(smc + SM_W1 + swz(toff(j + 1, k))) = __float2half_rn(w.y);
            *reinterpret_cast<__half*>(smc + SM_W1 + swz(toff(j + 2, k))) = __float2half_rn(w.z);
            *reinterpret_cast<__half*>(smc + SM_W1 + swz(toff(j + 3, k))) = __float2half_rn(w.w);
        }
        #pragma unroll
        for (int l = 0; l < 2; l++) {
            const float* Wp = Wh + ((size_t)l * 32 + o) * 128 * 128;
            const int base = l ? SM_WH1 : SM_WH0;
            for (int idx = tid; idx < 128 * 128 / 4; idx += THREADS) {
                int k = idx >> 5, j = (idx & 31) << 2;
                float4 w = reinterpret_cast<const float4*>(Wp)[idx];
                *reinterpret_cast<__half*>(smc + base + swz(toff(j + 0, k))) = __float2half_rn(w.x);
                *reinterpret_cast<__half*>(smc + base + swz(toff(j + 1, k))) = __float2half_rn(w.y);
                *reinterpret_cast<__half*>(smc + base + swz(toff(j + 2, k))) = __float2half_rn(w.z);
                *reinterpret_cast<__half*>(smc + base + swz(toff(j + 3, k))) = __float2half_rn(w.w);
            }
        }
    }
    __syncthreads();

    // biases/head weights via __ldg (L2-resident)
    const float* bias0 = b1 + o * 128;
    const float* bias1 = bh + (size_t)o * 128;
    const float* bias2 = bh + ((size_t)32 + o) * 128;
    const float* wo    = Wo + o * 128;
    float* pa = reinterpret_cast<float*>(smc + SM_PARTOFF + rg * 4096);

    // ---- ldmatrix lane addressing ----
    const int ra0 = rg * 32 + ((lane >> 3) & 1) * 8 + (lane & 7);
    const uint32_t aP0 = (uint32_t)(((ra0 >> 3) << 10) | ((ra0 & 7) << 7));
    const uint32_t aX  = (uint32_t)((lane & 7) << 4);
    const int ka = (lane >> 4) * 8;
    const int quad = lane >> 3;
    const int nb   = ((quad >> 1) << 3) + (lane & 7);
    const int kb4  = (quad & 1) << 3;
    const uint32_t bRow0 = (uint32_t)(((wq * 4 + (nb >> 3)) << 10) | ((nb & 7) << 7));
    const uint32_t bX    = (uint32_t)((lane & 7) << 4);

    const uint32_t actB = smb + SM_ACT;
    const int q = lane >> 2;

    for (int t = 0; t < TILES_PER_CTA; t++) {
        const int m0 = (g * TILES_PER_CTA + t) * 128;

        // ---- stage X rows for this group: [32 rows x 64 k] fp32 -> fp16 ----
        {
            const int p = wq * 32 + lane;             // 0..127 within group
            const int r = rg * 32 + (p >> 2);         // row
            const int kbx = (p & 3) << 4;             // k base
            const float4* xp = reinterpret_cast<const float4*>(x + (size_t)(m0 + r) * 64 + kbx);
            #pragma unroll
            for (int qq = 0; qq < 4; qq++) {
                float4 v = xp[qq];
                __half2 hh01 = __halves2half2(__float2half_rn(v.x), __float2half_rn(v.y));
                __half2 hh23 = __halves2half2(__float2half_rn(v.z), __float2half_rn(v.w));
                uint32_t off0 = swz(toff(r, kbx + 4 * qq));
                uint32_t off1 = swz(toff(r, kbx + 4 * qq + 2));
                *reinterpret_cast<uint32_t*>(smc + SM_ACT + off0) = *reinterpret_cast<uint32_t*>(&hh01);
                *reinterpret_cast<uint32_t*>(smc + SM_ACT + off1) = *reinterpret_cast<uint32_t*>(&hh23);
            }
        }
        BARG(barid);                 // (1) X visible

        // ---- layers 0 and 1: MMA then in-place epilogue ----
        #pragma unroll
        for (int l = 0; l < 2; l++) {
            float acc[2][4][4];
            #pragma unroll
            for (int mt = 0; mt < 2; mt++)
                #pragma unroll
                for (int nt = 0; nt < 4; nt++)
                    #pragma unroll
                    for (int e = 0; e < 4; e++) acc[mt][nt][e] = 0.0f;

            if (l == 0)
                layer_mma<4>(acc, actB, smb + SM_W1,  aP0, aX, ka, bRow0, bX, kb4);
            else
                layer_mma<8>(acc, actB, smb + SM_WH0, aP0, aX, ka, bRow0, bX, kb4);

            BARG(barid);             // group done reading act before rewrite
            const float* bias = (l == 0) ? bias0 : bias1;
            #pragma unroll
            for (int mt = 0; mt < 2; mt++) {
                const uint32_t rp0 = (uint32_t)(((rg * 4 + mt * 2) << 10) | (q << 7));
                const uint32_t rp1 = rp0 + (1u << 10);
                #pragma unroll
                for (int nt = 0; nt < 4; nt++) {
                    const int cc = wq * 32 + nt * 8 + (lane & 3) * 2;
                    const float2 bv = __ldg(reinterpret_cast<const float2*>(bias + cc));
                    float s0 = swishf(acc[mt][nt][0] + bv.x);
                    float s1 = swishf(acc[mt][nt][1] + bv.y);
                    float s2 = swishf(acc[mt][nt][2] + bv.x);
                    float s3 = swishf(acc[mt][nt][3] + bv.y);
                    __half2 hh01 = __halves2half2(__float2half_rn(s0), __float2half_rn(s1));
                    __half2 hh23 = __halves2half2(__float2half_rn(s2), __float2half_rn(s3));
                    const uint32_t kx = (uint32_t)(((cc >> 6) << 14) +
                                        (((cc & 63) << 1) ^ (q << 4)));
                    *reinterpret_cast<uint32_t*>(smc + SM_ACT + rp0 + kx) = *reinterpret_cast<uint32_t*>(&hh01);
                    *reinterpret_cast<uint32_t*>(smc + SM_ACT + rp1 + kx) = *reinterpret_cast<uint32_t*>(&hh23);
                }
            }
            BARG(barid);             // writes visible before next layer's reads
        }

        // ---- layer 2 + fused scalar head ----
        {
            float acc[2][4][4];
            #pragma unroll
            for (int mt = 0; mt < 2; mt++)
                #pragma unroll
                for (int nt = 0; nt < 4; nt++)
                    #pragma unroll
                    for (int e = 0; e < 4; e++) acc[mt][nt][e] = 0.0f;

            layer_mma<8>(acc, actB, smb + SM_WH1, aP0, aX, ka, bRow0, bX, kb4);

            float ps[4] = {0.f, 0.f, 0.f, 0.f};
            #pragma unroll
            for (int mt = 0; mt < 2; mt++) {
                #pragma unroll
                for (int nt = 0; nt < 4; nt++) {
                    const int cc = wq * 32 + nt * 8 + (lane & 3) * 2;
                    const float2 bv = __ldg(reinterpret_cast<const float2*>(bias2 + cc));
                    const float2 wv = __ldg(reinterpret_cast<const float2*>(wo + cc));
                    ps[mt * 2 + 0] += swishf(acc[mt][nt][0] + bv.x) * wv.x
                                    + swishf(acc[mt][nt][1] + bv.y) * wv.y;
                    ps[mt * 2 + 1] += swishf(acc[mt][nt][2] + bv.x) * wv.x
                                    + swishf(acc[mt][nt][3] + bv.y) * wv.y;
                }
            }
            #pragma unroll
            for (int i = 0; i < 4; i++) {
                ps[i] += __shfl_xor_sync(0xffffffffu, ps[i], 1);
                ps[i] += __shfl_xor_sync(0xffffffffu, ps[i], 2);
            }
            BARG(barid);             // group's layer-2 act reads done -> pa reusable
            if ((lane & 3) == 0) {
                const int r = lane >> 2;              // 0..7
                float* sp = pa + wq * 32;
                sp[r]      = ps[0];
                sp[r + 8]  = ps[1];
                sp[r + 16] = ps[2];
                sp[r + 24] = ps[3];
            }
            BARG(barid);             // pa visible
            if (wq == 0) {
                float v = pa[lane] + pa[32 + lane] + pa[64 + lane] + pa[96 + lane];
                out[(size_t)(m0 + rg * 32 + lane) * 32 + o] = v + __ldg(bo + o);
            }
            // next tile's staging writes only bytes [0,16384) (k<64), disjoint
            // from pa; barrier (1) orders everything else.
        }
    }
}

extern "C" void kernel_launch(void* const* d_in, const int* in_sizes, int n_in,
                              void* d_out, int out_size) {
    const float* x  = (const float*)d_in[0];
    const float* W1 = (const float*)d_in[1];
    const float* b1 = (const float*)d_in[2];
    const float* Wh = (const float*)d_in[3];
    const float* bh = (const float*)d_in[4];
    const float* Wo = (const float*)d_in[5];
    const float* bo = (const float*)d_in[6];
    float* out = (float*)d_out;

    cudaFuncSetAttribute(mlp_fused_kernel,
                         cudaFuncAttributeMaxDynamicSharedMemorySize, SM_TOTAL);
    mlp_fused_kernel<<<1024, THREADS, SM_TOTAL>>>(x, W1, b1, Wh, bh, Wo, bo, out);
}

// round 16
// speedup vs baseline: 1.4439x; 1.1728x over previous
#include <cuda_runtime.h>
#include <cuda_fp16.h>
#include <cstdint>

// ============================================================
// SparseModel: 32 MLPs (64 -> 128 -> 128 -> 128 -> 1, swish)
// R11 base (dual-M-tile HMMA fp16, tanh-swish, 16 warps = 4rg x 4wq)
// + parity-swapped buffers: next tile's X staged during L2 phase
//   (3 barriers/tile, global-load latency hidden)
// + packed cvt.rn.f16x2.f32 conversions.
// ============================================================

#define THREADS 512
#define GROUPS 32
#define DBL_TILES 4          // 4 x 256 rows per CTA

// ---- smem layout ----
static constexpr int SM_A0 = 0;         // tile A, buffer 0 [128x128 fp16]
static constexpr int SM_B0 = 32768;     // tile B, buffer 0
static constexpr int SM_A1 = 65536;     // tile A, buffer 1
static constexpr int SM_B1 = 98304;     // tile B, buffer 1
static constexpr int SM_W1    = 131072; // W1  [128n x 64k fp16]
static constexpr int SM_WH0   = 147456; // Wh0 [128n x 128k fp16]
static constexpr int SM_WH1   = 180224;
static constexpr int SM_PART  = 212992;          // 2 x 512 floats
static constexpr int SM_BIAS  = SM_PART + 4096;  // 3 x 128 floats
static constexpr int SM_WO    = SM_BIAS + 1536;  // 128 floats
static constexpr int SM_TOTAL = SM_WO + 512;     // 219136 <= 232448

// ---- helpers ----
__device__ __forceinline__ uint32_t smem_to_u32(const void* p) {
    uint32_t a;
    asm("{ .reg .u64 t; cvta.to.shared.u64 t, %1; cvt.u32.u64 %0, t; }" : "=r"(a) : "l"(p));
    return a;
}
__device__ __forceinline__ uint32_t swz(uint32_t b) { return b ^ ((b >> 3) & 0x70u); }
__device__ __forceinline__ uint32_t toff(int r, int k) {
    return (uint32_t)(((((k >> 6) << 4) + (r >> 3)) << 10) | ((r & 7) << 7) | ((k & 63) << 1));
}
// packed half2 = {lo, hi} in ONE cvt (PTX: first source -> upper half)
__device__ __forceinline__ uint32_t pack_h2(float lo, float hi) {
    uint32_t r;
    asm("cvt.rn.f16x2.f32 %0, %1, %2;" : "=r"(r) : "f"(hi), "f"(lo));
    return r;
}

#define LDSM_X4(r, addr) \
    asm volatile("ldmatrix.sync.aligned.m8n8.x4.shared.b16 {%0,%1,%2,%3}, [%4];" \
        : "=r"((r)[0]), "=r"((r)[1]), "=r"((r)[2]), "=r"((r)[3]) : "r"(addr))
#define MMA16816(d, a, b) \
    asm volatile("mma.sync.aligned.m16n8k16.row.col.f32.f16.f16.f32 " \
        "{%0,%1,%2,%3}, {%4,%5,%6,%7}, {%8,%9}, {%0,%1,%2,%3};" \
        : "+f"((d)[0]), "+f"((d)[1]), "+f"((d)[2]), "+f"((d)[3]) \
        : "r"((a)[0]), "r"((a)[1]), "r"((a)[2]), "r"((a)[3]), "r"((b)[0]), "r"((b)[1]))
#define BARG(id) asm volatile("bar.sync %0, 128;" :: "r"(id) : "memory")

// swish: swish(v) = h*tanh(h)+h with h = v/2   (1 MUFU)
__device__ __forceinline__ float swishf(float v) {
    float t;
    const float h = 0.5f * v;
    asm("tanh.approx.f32 %0, %1;" : "=f"(t) : "f"(h));
    return fmaf(h, t, h);
}

// dual-tile layer mainloop: acc[tile][mt][nt][e]
template <int NCH>
__device__ __forceinline__ void layer_mma2(
    float acc[2][2][4][4], uint32_t srcA, uint32_t srcB, uint32_t wB,
    uint32_t aP0, uint32_t aP1, uint32_t aX, int ka,
    uint32_t bRow0, uint32_t bX, int kb4)
{
    #pragma unroll
    for (int c = 0; c < NCH; ++c) {
        const uint32_t kA  = (uint32_t)(c * 16 + ka);
        const uint32_t kxA = ((kA >> 6) << 14) + (((kA & 63) << 1) ^ aX);
        const uint32_t kB  = (uint32_t)(c * 16 + kb4);
        const uint32_t kxB = ((kB >> 6) << 14) + (((kB & 63) << 1) ^ bX);

        uint32_t bf[4][2];
        #pragma unroll
        for (int np = 0; np < 2; np++) {
            uint32_t q4[4];
            LDSM_X4(q4, wB + bRow0 + ((uint32_t)np << 11) + kxB);
            bf[2*np][0]   = q4[0]; bf[2*np][1]   = q4[1];
            bf[2*np+1][0] = q4[2]; bf[2*np+1][1] = q4[3];
        }
        uint32_t a0A[4], a1A[4], a0B[4], a1B[4];
        LDSM_X4(a0A, srcA + aP0 + kxA);
        LDSM_X4(a1A, srcA + aP1 + kxA);
        LDSM_X4(a0B, srcB + aP0 + kxA);
        LDSM_X4(a1B, srcB + aP1 + kxA);

        #pragma unroll
        for (int nt = 0; nt < 4; nt++) {
            MMA16816(acc[0][0][nt], a0A, bf[nt]);
            MMA16816(acc[0][1][nt], a1A, bf[nt]);
            MMA16816(acc[1][0][nt], a0B, bf[nt]);
            MMA16816(acc[1][1][nt], a1B, bf[nt]);
        }
    }
}

// stage X [2 x 128 rows x 64 k] fp32 -> fp16 into (dstA, dstB)
__device__ __forceinline__ void stage_x(
    const float* __restrict__ x, int m0, char* smc,
    int dstA, int dstB, int rg, int wq, int lane)
{
    const int p = wq * 32 + lane;             // 0..127 within group
    const int r = rg * 32 + (p >> 2);
    const int kbx = (p & 3) << 4;
    #pragma unroll
    for (int tt = 0; tt < 2; tt++) {
        const float4* xp = reinterpret_cast<const float4*>(
            x + (size_t)(m0 + tt * 128 + r) * 64 + kbx);
        const int dst = tt ? dstB : dstA;
        #pragma unroll
        for (int qq = 0; qq < 4; qq++) {
            float4 v = xp[qq];
            uint32_t h01 = pack_h2(v.x, v.y);
            uint32_t h23 = pack_h2(v.z, v.w);
            uint32_t off0 = swz(toff(r, kbx + 4 * qq));
            uint32_t off1 = swz(toff(r, kbx + 4 * qq + 2));
            *reinterpret_cast<uint32_t*>(smc + dst + off0) = h01;
            *reinterpret_cast<uint32_t*>(smc + dst + off1) = h23;
        }
    }
}

__global__ void __launch_bounds__(THREADS, 1)
mlp_fused_kernel(const float* __restrict__ x,  const float* __restrict__ W1,
                 const float* __restrict__ b1, const float* __restrict__ Wh,
                 const float* __restrict__ bh, const float* __restrict__ Wo,
                 const float* __restrict__ bo, float* __restrict__ out)
{
    extern __shared__ char smc[];
    const uint32_t smb = smem_to_u32(smc);
    const int tid = threadIdx.x;
    const int wid = tid >> 5;
    const int lane = tid & 31;
    const int o = blockIdx.x & 31;       // subnet
    const int g = blockIdx.x >> 5;       // group of 1024 rows

    const int rg = wid >> 2;             // row group (32 rows)
    const int wq = wid & 3;              // column quarter (32 cols)
    const int barid = 1 + rg;            // named barriers 1..4 (128 threads each)

    // ---- stage weights (fp16, single rounding) ----
    {
        const float* W1p = W1 + o * 64 * 128;
        for (int idx = tid; idx < 64 * 128; idx += THREADS) {
            int k = idx >> 7, j = idx & 127;         // W1[o][k][j] -> B[n=j][k]
            *reinterpret_cast<__half*>(smc + SM_W1 + swz(toff(j, k))) = __float2half_rn(W1p[idx]);
        }
        #pragma unroll
        for (int l = 0; l < 2; l++) {
            const float* Wp = Wh + ((size_t)l * 32 + o) * 128 * 128;
            const int base = l ? SM_WH1 : SM_WH0;
            for (int idx = tid; idx < 128 * 128; idx += THREADS) {
                int k = idx >> 7, j = idx & 127;
                *reinterpret_cast<__half*>(smc + base + swz(toff(j, k))) = __float2half_rn(Wp[idx]);
            }
        }
        for (int j = tid; j < 128; j += THREADS) {
            reinterpret_cast<float*>(smc + SM_BIAS)[j]       = b1[o * 128 + j];
            reinterpret_cast<float*>(smc + SM_BIAS)[128 + j] = bh[(size_t)o * 128 + j];
            reinterpret_cast<float*>(smc + SM_BIAS)[256 + j] = bh[((size_t)32 + o) * 128 + j];
            reinterpret_cast<float*>(smc + SM_WO)[j]         = Wo[o * 128 + j];
        }
    }
    __syncthreads();

    const float bo_v   = bo[o];
    const float* sbias = reinterpret_cast<const float*>(smc + SM_BIAS);
    const float* sWo   = reinterpret_cast<const float*>(smc + SM_WO);
    float* sPart       = reinterpret_cast<float*>(smc + SM_PART);

    // ---- ldmatrix lane addressing ----
    const int ra0 = rg * 32 + ((lane >> 3) & 1) * 8 + (lane & 7);
    const uint32_t aP0 = (uint32_t)(((ra0 >> 3) << 10) | ((ra0 & 7) << 7));
    const uint32_t aP1 = aP0 + (2u << 10);             // +16 rows
    const uint32_t aX  = (uint32_t)((lane & 7) << 4);
    const int ka = (lane >> 4) * 8;
    const int quad = lane >> 3;
    const int nb   = ((quad >> 1) << 3) + (lane & 7);
    const int kb4  = (quad & 1) << 3;
    const uint32_t bRow0 = (uint32_t)(((wq * 4 + (nb >> 3)) << 10) | ((nb & 7) << 7));
    const uint32_t bX    = (uint32_t)((lane & 7) << 4);

    const int q = lane >> 2;
    const int bufA[2] = { SM_A0, SM_A1 };
    const int bufB[2] = { SM_B0, SM_B1 };

    // ---- prologue: stage tile 0 into buffer 0 ----
    stage_x(x, g * DBL_TILES * 256, smc, SM_A0, SM_B0, rg, wq, lane);
    BARG(barid);

    for (int t = 0; t < DBL_TILES; t++) {
        const int m0 = (g * DBL_TILES + t) * 256;
        const int p = t & 1;

        // ---- layer 0: src buf[p] -> dst buf[1-p] ----
        {
            float acc[2][2][4][4];
            #pragma unroll
            for (int tt = 0; tt < 2; tt++)
                #pragma unroll
                for (int mt = 0; mt < 2; mt++)
                    #pragma unroll
                    for (int nt = 0; nt < 4; nt++)
                        #pragma unroll
                        for (int e = 0; e < 4; e++) acc[tt][mt][nt][e] = 0.0f;

            layer_mma2<4>(acc, smb + bufA[p], smb + bufB[p], smb + SM_W1,
                          aP0, aP1, aX, ka, bRow0, bX, kb4);

            const float* bias = sbias;
            #pragma unroll
            for (int tt = 0; tt < 2; tt++) {
                const int dst = tt ? bufB[1 - p] : bufA[1 - p];
                #pragma unroll
                for (int mt = 0; mt < 2; mt++) {
                    const uint32_t rp0 = (uint32_t)(((rg * 4 + mt * 2) << 10) | (q << 7));
                    const uint32_t rp1 = rp0 + (1u << 10);
                    #pragma unroll
                    for (int nt = 0; nt < 4; nt++) {
                        const int cc = wq * 32 + nt * 8 + (lane & 3) * 2;
                        const float b0v = bias[cc], b1v = bias[cc + 1];
                        float s0 = swishf(acc[tt][mt][nt][0] + b0v);
                        float s1 = swishf(acc[tt][mt][nt][1] + b1v);
                        float s2 = swishf(acc[tt][mt][nt][2] + b0v);
                        float s3 = swishf(acc[tt][mt][nt][3] + b1v);
                        const uint32_t kx = (uint32_t)(((cc >> 6) << 14) +
                                            (((cc & 63) << 1) ^ (q << 4)));
                        *reinterpret_cast<uint32_t*>(smc + dst + rp0 + kx) = pack_h2(s0, s1);
                        *reinterpret_cast<uint32_t*>(smc + dst + rp1 + kx) = pack_h2(s2, s3);
                    }
                }
            }
            BARG(barid);             // (1) L0 output visible
        }

        // ---- layer 1: src buf[1-p] -> dst buf[p] ----
        {
            float acc[2][2][4][4];
            #pragma unroll
            for (int tt = 0; tt < 2; tt++)
                #pragma unroll
                for (int mt = 0; mt < 2; mt++)
                    #pragma unroll
                    for (int nt = 0; nt < 4; nt++)
                        #pragma unroll
                        for (int e = 0; e < 4; e++) acc[tt][mt][nt][e] = 0.0f;

            layer_mma2<8>(acc, smb + bufA[1 - p], smb + bufB[1 - p], smb + SM_WH0,
                          aP0, aP1, aX, ka, bRow0, bX, kb4);

            const float* bias = sbias + 128;
            #pragma unroll
            for (int tt = 0; tt < 2; tt++) {
                const int dst = tt ? bufB[p] : bufA[p];
                #pragma unroll
                for (int mt = 0; mt < 2; mt++) {
                    const uint32_t rp0 = (uint32_t)(((rg * 4 + mt * 2) << 10) | (q << 7));
                    const uint32_t rp1 = rp0 + (1u << 10);
                    #pragma unroll
                    for (int nt = 0; nt < 4; nt++) {
                        const int cc = wq * 32 + nt * 8 + (lane & 3) * 2;
                        const float b0v = bias[cc], b1v = bias[cc + 1];
                        float s0 = swishf(acc[tt][mt][nt][0] + b0v);
                        float s1 = swishf(acc[tt][mt][nt][1] + b1v);
                        float s2 = swishf(acc[tt][mt][nt][2] + b0v);
                        float s3 = swishf(acc[tt][mt][nt][3] + b1v);
                        const uint32_t kx = (uint32_t)(((cc >> 6) << 14) +
                                            (((cc & 63) << 1) ^ (q << 4)));
                        *reinterpret_cast<uint32_t*>(smc + dst + rp0 + kx) = pack_h2(s0, s1);
                        *reinterpret_cast<uint32_t*>(smc + dst + rp1 + kx) = pack_h2(s2, s3);
                    }
                }
            }
            BARG(barid);             // (2) L1 output visible; buf[1-p] now dead
        }

        // ---- overlap: stage NEXT tile's X into the dead buffer buf[1-p] ----
        if (t < DBL_TILES - 1)
            stage_x(x, m0 + 256, smc, bufA[1 - p], bufB[1 - p], rg, wq, lane);

        // ---- layer 2 + fused scalar head (reads buf[p]) ----
        {
            float acc[2][2][4][4];
            #pragma unroll
            for (int tt = 0; tt < 2; tt++)
                #pragma unroll
                for (int mt = 0; mt < 2; mt++)
                    #pragma unroll
                    for (int nt = 0; nt < 4; nt++)
                        #pragma unroll
                        for (int e = 0; e < 4; e++) acc[tt][mt][nt][e] = 0.0f;

            layer_mma2<8>(acc, smb + bufA[p], smb + bufB[p], smb + SM_WH1,
                          aP0, aP1, aX, ka, bRow0, bX, kb4);

            #pragma unroll
            for (int tt = 0; tt < 2; tt++) {
                float ps[4] = {0.f, 0.f, 0.f, 0.f};
                #pragma unroll
                for (int mt = 0; mt < 2; mt++) {
                    #pragma unroll
                    for (int nt = 0; nt < 4; nt++) {
                        const int cc = wq * 32 + nt * 8 + (lane & 3) * 2;
                        const float b0v = sbias[256 + cc], b1v = sbias[256 + cc + 1];
                        const float w0 = sWo[cc], w1 = sWo[cc + 1];
                        ps[mt * 2 + 0] += swishf(acc[tt][mt][nt][0] + b0v) * w0
                                        + swishf(acc[tt][mt][nt][1] + b1v) * w1;
                        ps[mt * 2 + 1] += swishf(acc[tt][mt][nt][2] + b0v) * w0
                                        + swishf(acc[tt][mt][nt][3] + b1v) * w1;
                    }
                }
                #pragma unroll
                for (int i = 0; i < 4; i++) {
                    ps[i] += __shfl_xor_sync(0xffffffffu, ps[i], 1);
                    ps[i] += __shfl_xor_sync(0xffffffffu, ps[i], 2);
                }
                if ((lane & 3) == 0) {
                    const int r = lane >> 2;
                    float* sp = sPart + tt * 512 + rg * 128 + wq * 32;
                    sp[r]      = ps[0];
                    sp[r + 8]  = ps[1];
                    sp[r + 16] = ps[2];
                    sp[r + 24] = ps[3];
                }
            }
            BARG(barid);             // (3) sPart + staged X visible
            if (wq == 0) {
                #pragma unroll
                for (int tt = 0; tt < 2; tt++) {
                    const float* sp = sPart + tt * 512 + rg * 128;
                    float v = sp[lane] + sp[32 + lane] + sp[64 + lane] + sp[96 + lane];
                    out[(size_t)(m0 + tt * 128 + rg * 32 + lane) * 32 + o] = v + bo_v;
                }
            }
        }
    }
}

extern "C" void kernel_launch(void* const* d_in, const int* in_sizes, int n_in,
                              void* d_out, int out_size) {
    const float* x  = (const float*)d_in[0];
    const float* W1 = (const float*)d_in[1];
    const float* b1 = (const float*)d_in[2];
    const float* Wh = (const float*)d_in[3];
    const float* bh = (const float*)d_in[4];
    const float* Wo = (const float*)d_in[5];
    const float* bo = (const float*)d_in[6];
    float* out = (float*)d_out;

    cudaFuncSetAttribute(mlp_fused_kernel,
                         cudaFuncAttributeMaxDynamicSharedMemorySize, SM_TOTAL);
    mlp_fused_kernel<<<GROUPS * 32, THREADS, SM_TOTAL>>>(x, W1, b1, Wh, bh, Wo, bo, out);
}